// round 6
// baseline (speedup 1.0000x reference)
#include <cuda_runtime.h>
#include <cuda_fp16.h>
#include <math.h>
#include <stdint.h>

// ---------------- problem constants ----------------
#define L_SEQ 2048
#define DM    1024
#define DI    2048
#define NST   16
#define KC    4
#define NPROJ (DI + 2*NST)   // 2080

#define NCH   16
#define CH    128
#define TT    16
#define SD    64

// ---------------- scratch (device globals) ----------------
__device__ float g_xr  [L_SEQ * 2 * DI];
__device__ float g_xi  [L_SEQ * DI];
__device__ float g_proj[L_SEQ * NPROJ];

__device__ __half g_ahi[L_SEQ * DI];         // activation hi (fp16)
__device__ __half g_alo[L_SEQ * DI];         // activation lo (fp16)
__device__ __half g_win_h [2 * DI * DM];     // W_in  fp16
__device__ __half g_wx_h  [NPROJ * DI];      // W_x   fp16
__device__ __half g_wout_h[DM * DI];         // W_out fp16

__device__ float g_cA[NCH * DI * NST];
__device__ float g_cB[NCH * DI * NST];
__device__ float g_h0[NCH * DI * NST];

__device__ __forceinline__ float softplus_f(float x) {
    return fmaxf(x, 0.f) + log1pf(expf(-fabsf(x)));
}

// ---------------- PTX helpers ----------------
__device__ __forceinline__ uint32_t smem_u32(const void* p) {
    uint32_t a;
    asm("{ .reg .u64 t; cvta.to.shared.u64 t, %1; cvt.u32.u64 %0, t; }" : "=r"(a) : "l"(p));
    return a;
}
__device__ __forceinline__ void cp_async16(uint32_t sm, const void* gm) {
    asm volatile("cp.async.ca.shared.global [%0], [%1], 16;" :: "r"(sm), "l"(gm));
}
__device__ __forceinline__ void cp_async16p(void* sm, const void* gm) {
    cp_async16(smem_u32(sm), gm);
}
__device__ __forceinline__ void cp_commit() { asm volatile("cp.async.commit_group;"); }
template<int N> __device__ __forceinline__ void cp_wait() {
    asm volatile("cp.async.wait_group %0;" :: "n"(N));
}
__device__ __forceinline__ void ldm_x4(uint32_t* r, uint32_t addr) {
    asm volatile("ldmatrix.sync.aligned.m8n8.x4.shared.b16 {%0,%1,%2,%3}, [%4];"
        : "=r"(r[0]), "=r"(r[1]), "=r"(r[2]), "=r"(r[3]) : "r"(addr));
}
__device__ __forceinline__ void mma_f16(float* d, const uint32_t* a, const uint32_t* b) {
    asm volatile(
        "mma.sync.aligned.m16n8k16.row.col.f32.f16.f16.f32 "
        "{%0,%1,%2,%3}, {%4,%5,%6,%7}, {%8,%9}, {%0,%1,%2,%3};"
        : "+f"(d[0]), "+f"(d[1]), "+f"(d[2]), "+f"(d[3])
        : "r"(a[0]), "r"(a[1]), "r"(a[2]), "r"(a[3]), "r"(b[0]), "r"(b[1]));
}

// ============================================================================
// One fused convert kernel: all weights -> fp16, x -> fp16 hi/lo.
// Region map over float4 tasks.
// ============================================================================
#define N4_X   (L_SEQ * DM / 4)          // 524288
#define N4_WIN (2 * DI * DM / 4)         // 1048576
#define N4_WX  (NPROJ * DI / 4)          // 1064960
#define N4_WO  (DM * DI / 4)             // 524288
#define N4_TOT (N4_X + N4_WIN + N4_WX + N4_WO)

__global__ __launch_bounds__(256)
void cvt_all(const float* __restrict__ x, const float* __restrict__ W_in,
             const float* __restrict__ W_x, const float* __restrict__ W_out)
{
    int i = blockIdx.x * blockDim.x + threadIdx.x;
    if (i >= N4_TOT) return;

    if (i < N4_X) {
        float4 v = ((const float4*)x)[i];
        __half hx = __float2half_rn(v.x), hy = __float2half_rn(v.y);
        __half hz = __float2half_rn(v.z), hw = __float2half_rn(v.w);
        ((__half2*)g_ahi)[i*2+0] = __half2(hx, hy);
        ((__half2*)g_ahi)[i*2+1] = __half2(hz, hw);
        ((__half2*)g_alo)[i*2+0] = __half2(__float2half_rn(v.x - __half2float(hx)),
                                           __float2half_rn(v.y - __half2float(hy)));
        ((__half2*)g_alo)[i*2+1] = __half2(__float2half_rn(v.z - __half2float(hz)),
                                           __float2half_rn(v.w - __half2float(hw)));
        return;
    }
    const float* src; __half* dst; int j;
    if (i < N4_X + N4_WIN)              { j = i - N4_X;            src = W_in;  dst = g_win_h; }
    else if (i < N4_X + N4_WIN + N4_WX) { j = i - N4_X - N4_WIN;   src = W_x;   dst = g_wx_h; }
    else                                { j = i - N4_X - N4_WIN - N4_WX; src = W_out; dst = g_wout_h; }
    float4 v = ((const float4*)src)[j];
    ((__half2*)dst)[j*2+0] = __half2(__float2half_rn(v.x), __float2half_rn(v.y));
    ((__half2*)dst)[j*2+1] = __half2(__float2half_rn(v.z), __float2half_rn(v.w));
}

// ============================================================================
// fp16 2-term emulated-fp32 GEMM via mma.sync m16n8k16.
// Block 128x128, BK=32, 8 warps. 3-stage cp.async ring, ONE barrier/iter.
// ============================================================================
#define ROWEL 40
#define MATB  (128 * ROWEL * 2)
#define BUFB  (3 * MATB)
#define GEMM_SMEM (3 * BUFB)   // 92160

__device__ __forceinline__ void gemm_load_stage(
    uint32_t sb, int buf, int k0,
    const __half* __restrict__ Ahi, const __half* __restrict__ Alo,
    const __half* __restrict__ Wh,
    int m0, int n0, int Nc, int Kd, int tid)
{
    uint32_t base = sb + buf * BUFB;
#pragma unroll
    for (int it = 0; it < 6; it++) {
        int q   = tid + it * 256;
        int mat = q >> 9;
        int rem = q & 511;
        int row = rem >> 2;
        int ch  = rem & 3;
        uint32_t dst = base + mat * MATB + row * (ROWEL * 2) + ch * 16;
        const __half* src;
        if (mat < 2) {
            const __half* bp = (mat == 0) ? Ahi : Alo;
            src = bp + (size_t)(m0 + row) * Kd + k0 + ch * 8;
        } else {
            int wr = n0 + row; if (wr >= Nc) wr = Nc - 1;
            src = Wh + (size_t)wr * Kd + k0 + ch * 8;
        }
        cp_async16(dst, src);
    }
    cp_commit();
}

template<int ACT>
__global__ __launch_bounds__(256, 2)
void gemm_mma(const __half* __restrict__ Ahi, const __half* __restrict__ Alo,
              const __half* __restrict__ Wh,
              const float* __restrict__ bias, float* __restrict__ C,
              int Nc, int Kd, int ldc)
{
    extern __shared__ char smraw[];
    uint32_t sb = smem_u32(smraw);

    int tid  = threadIdx.x;
    int wid  = tid >> 5;
    int lane = tid & 31;
    int wm   = wid & 3;
    int wn   = wid >> 2;
    int m0 = blockIdx.y * 128;
    int n0 = blockIdx.x * 128;

    float acc[2][8][4];
#pragma unroll
    for (int i = 0; i < 2; i++)
#pragma unroll
        for (int j = 0; j < 8; j++)
#pragma unroll
            for (int k = 0; k < 4; k++) acc[i][j][k] = 0.f;

    int aRow = wm * 32 + (lane & 15);
    int aColHalf = (lane >> 4) << 3;
    int bRow = wn * 64 + ((lane >> 4) & 1) * 8 + (lane & 7);
    int bColHalf = ((lane >> 3) & 1) << 3;

    const int NSTAGE = Kd / 32;
    gemm_load_stage(sb, 0, 0,  Ahi, Alo, Wh, m0, n0, Nc, Kd, tid);
    gemm_load_stage(sb, 1, 32, Ahi, Alo, Wh, m0, n0, Nc, Kd, tid);

    int bufs = 0;
    for (int s = 0; s < NSTAGE; s++) {
        // wait for stage s to be resident
        if (s + 1 < NSTAGE) cp_wait<1>(); else cp_wait<0>();
        __syncthreads();
        // safe to overwrite buffer (bufs+2)%3: all warps passed the sync,
        // so compute of iter s-1 (its only reader) is complete.
        if (s + 2 < NSTAGE)
            gemm_load_stage(sb, (bufs + 2) % 3, (s + 2) * 32, Ahi, Alo, Wh, m0, n0, Nc, Kd, tid);

        uint32_t bA = sb + bufs * BUFB;
        uint32_t bW = bA + 2 * MATB;
#pragma unroll
        for (int kc = 0; kc < 2; kc++) {
            int acol = kc * 16 + aColHalf;
            int bcol = kc * 16 + bColHalf;
            uint32_t ah[2][4], al[2][4];
#pragma unroll
            for (int mt = 0; mt < 2; mt++) {
                uint32_t off = (uint32_t)((aRow + mt * 16) * (ROWEL * 2) + acol * 2);
                ldm_x4(ah[mt], bA + off);
                ldm_x4(al[mt], bA + MATB + off);
            }
#pragma unroll
            for (int ntp = 0; ntp < 4; ntp++) {
                uint32_t off = (uint32_t)((bRow + ntp * 16) * (ROWEL * 2) + bcol * 2);
                uint32_t bh[4];
                ldm_x4(bh, bW + off);
#pragma unroll
                for (int mt = 0; mt < 2; mt++) {
                    mma_f16(acc[mt][2*ntp+0], ah[mt], bh + 0);
                    mma_f16(acc[mt][2*ntp+1], ah[mt], bh + 2);
                    mma_f16(acc[mt][2*ntp+0], al[mt], bh + 0);
                    mma_f16(acc[mt][2*ntp+1], al[mt], bh + 2);
                }
            }
        }
        bufs = (bufs + 1) % 3;
    }

#pragma unroll
    for (int mt = 0; mt < 2; mt++) {
        int r0 = m0 + wm * 32 + mt * 16 + (lane >> 2);
#pragma unroll
        for (int nt = 0; nt < 8; nt++) {
            int c = n0 + wn * 64 + nt * 8 + 2 * (lane & 3);
            if (c < Nc) {
                float b0 = bias[c], b1 = bias[c + 1];
                float v0 = acc[mt][nt][0] + b0;
                float v1 = acc[mt][nt][1] + b1;
                float v2 = acc[mt][nt][2] + b0;
                float v3 = acc[mt][nt][3] + b1;
                if (ACT == 1) {
                    if (c     < DI) { v0 = softplus_f(v0); v2 = softplus_f(v2); }
                    if (c + 1 < DI) { v1 = softplus_f(v1); v3 = softplus_f(v3); }
                }
                *(float2*)&C[(size_t)r0 * ldc + c]       = make_float2(v0, v1);
                *(float2*)&C[(size_t)(r0 + 8) * ldc + c] = make_float2(v2, v3);
            }
        }
    }
}

// ============================================================================
// Depthwise causal conv (K=4) + silu, 4 channels/thread (float4).
// Writes fp32 xi AND fp16 hi/lo (GEMM2's A).
// ============================================================================
__global__ __launch_bounds__(256)
void conv_silu_k(const float* __restrict__ Wc, const float* __restrict__ bc)
{
    int idx = blockIdx.x * blockDim.x + threadIdx.x;  // over L*DI/4
    int t  = idx >> 9;            // / 512
    int d4 = (idx & 511) << 2;    // 0..2044 step 4

    float4 acc = *(const float4*)&bc[d4];
#pragma unroll
    for (int k = 0; k < KC; k++) {
        int tt = t - (KC - 1) + k;
        if (tt >= 0) {
            float4 v = *(const float4*)&g_xr[(size_t)tt * (2 * DI) + d4];
            acc.x = fmaf(Wc[(d4 + 0) * KC + k], v.x, acc.x);
            acc.y = fmaf(Wc[(d4 + 1) * KC + k], v.y, acc.y);
            acc.z = fmaf(Wc[(d4 + 2) * KC + k], v.z, acc.z);
            acc.w = fmaf(Wc[(d4 + 3) * KC + k], v.w, acc.w);
        }
    }
    float s0 = acc.x / (1.f + __expf(-acc.x));
    float s1 = acc.y / (1.f + __expf(-acc.y));
    float s2 = acc.z / (1.f + __expf(-acc.z));
    float s3 = acc.w / (1.f + __expf(-acc.w));
    size_t o = (size_t)t * DI + d4;
    *(float4*)&g_xi[o] = make_float4(s0, s1, s2, s3);
    __half h0 = __float2half_rn(s0), h1 = __float2half_rn(s1);
    __half h2 = __float2half_rn(s2), h3 = __float2half_rn(s3);
    *(__half2*)&g_ahi[o]     = __half2(h0, h1);
    *(__half2*)&g_ahi[o + 2] = __half2(h2, h3);
    *(__half2*)&g_alo[o]     = __half2(__float2half_rn(s0 - __half2float(h0)),
                                       __float2half_rn(s1 - __half2float(h1)));
    *(__half2*)&g_alo[o + 2] = __half2(__float2half_rn(s2 - __half2float(h2)),
                                       __float2half_rn(s3 - __half2float(h3)));
}

// ============================================================================
// Chunked selective scan, 4 states per thread (unchanged numerics).
// ============================================================================
__global__ __launch_bounds__(256, 1)
void scan_p1(const float* __restrict__ A_log)
{
    __shared__ float s_delta[2][TT][SD];
    __shared__ float s_xi   [2][TT][SD];
    __shared__ float s_B    [2][TT][NST];

    int tid = threadIdx.x;
    int nq = tid & 3;
    int dl = tid >> 2;
    int dbase = blockIdx.x * SD;
    int d = dbase + dl;
    int chunk = blockIdx.y;
    int tbase = chunk * CH;

    float4 alv = *(const float4*)&A_log[d * NST + nq * 4];
    float A0 = -__expf(alv.x), A1 = -__expf(alv.y);
    float A2 = -__expf(alv.z), A3 = -__expf(alv.w);

    float ap0 = 1.f, ap1 = 1.f, ap2 = 1.f, ap3 = 1.f;
    float h0 = 0.f, h1 = 0.f, h2 = 0.f, h3 = 0.f;

    auto issue = [&](int t0, int buf) {
        for (int q = tid; q < 576; q += 256) {
            if (q < 512) {
                int arr = q >> 8;
                int rem = q & 255;
                int tq  = rem >> 4;
                int v   = (rem & 15) * 4;
                int t   = tbase + t0 + tq;
                if (arr == 0)
                    cp_async16p(&s_delta[buf][tq][v], g_proj + (size_t)t * NPROJ + dbase + v);
                else
                    cp_async16p(&s_xi[buf][tq][v], g_xi + (size_t)t * DI + dbase + v);
            } else {
                int rem = q - 512;
                int tq  = rem >> 2;
                int v   = (rem & 3) * 4;
                int t   = tbase + t0 + tq;
                cp_async16p(&s_B[buf][tq][v], g_proj + (size_t)t * NPROJ + DI + v);
            }
        }
        cp_commit();
    };

    issue(0, 0);
    int buf = 0;
    const int NT = CH / TT;
    for (int it = 0; it < NT; it++) {
        if (it + 1 < NT) { issue((it + 1) * TT, buf ^ 1); cp_wait<1>(); }
        else             { cp_wait<0>(); }
        __syncthreads();
#pragma unroll
        for (int tt = 0; tt < TT; tt++) {
            float del = s_delta[buf][tt][dl];
            float xv  = s_xi[buf][tt][dl];
            float4 bv = *(const float4*)&s_B[buf][tt][nq * 4];
            float dx = del * xv;
            float e0 = __expf(del * A0), e1 = __expf(del * A1);
            float e2 = __expf(del * A2), e3 = __expf(del * A3);
            ap0 *= e0; ap1 *= e1; ap2 *= e2; ap3 *= e3;
            h0 = fmaf(e0, h0, dx * bv.x);
            h1 = fmaf(e1, h1, dx * bv.y);
            h2 = fmaf(e2, h2, dx * bv.z);
            h3 = fmaf(e3, h3, dx * bv.w);
        }
        __syncthreads();
        buf ^= 1;
    }
    int idx = (chunk * DI + d) * NST + nq * 4;
    *(float4*)&g_cA[idx] = make_float4(ap0, ap1, ap2, ap3);
    *(float4*)&g_cB[idx] = make_float4(h0, h1, h2, h3);
}

__global__ __launch_bounds__(256)
void scan_comb()
{
    int dn = blockIdx.x * blockDim.x + threadIdx.x;
    float h = 0.f;
#pragma unroll
    for (int c = 0; c < NCH; c++) {
        int idx = c * (DI * NST) + dn;
        g_h0[idx] = h;
        h = fmaf(g_cA[idx], h, g_cB[idx]);
    }
}

__global__ __launch_bounds__(256, 1)
void scan_p3(const float* __restrict__ A_log, const float* __restrict__ Dv)
{
    __shared__ float s_delta[2][TT][SD];
    __shared__ float s_xi   [2][TT][SD];
    __shared__ float s_res  [2][TT][SD];
    __shared__ float s_B    [2][TT][NST];
    __shared__ float s_C    [2][TT][NST];

    int tid = threadIdx.x;
    int nq = tid & 3;
    int dl = tid >> 2;
    int dbase = blockIdx.x * SD;
    int d = dbase + dl;
    int chunk = blockIdx.y;
    int tbase = chunk * CH;

    float4 alv = *(const float4*)&A_log[d * NST + nq * 4];
    float A0 = -__expf(alv.x), A1 = -__expf(alv.y);
    float A2 = -__expf(alv.z), A3 = -__expf(alv.w);
    float Dd = Dv[d];

    float4 hv = *(const float4*)&g_h0[(chunk * DI + d) * NST + nq * 4];
    float h0 = hv.x, h1 = hv.y, h2 = hv.z, h3 = hv.w;

    auto issue = [&](int t0, int buf) {
        for (int q = tid; q < 896; q += 256) {
            if (q < 768) {
                int arr = q >> 8;
                int rem = q & 255;
                int tq  = rem >> 4;
                int v   = (rem & 15) * 4;
                int t   = tbase + t0 + tq;
                if      (arr == 0) cp_async16p(&s_delta[buf][tq][v], g_proj + (size_t)t * NPROJ + dbase + v);
                else if (arr == 1) cp_async16p(&s_xi[buf][tq][v],    g_xi   + (size_t)t * DI + dbase + v);
                else               cp_async16p(&s_res[buf][tq][v],   g_xr   + (size_t)t * (2*DI) + DI + dbase + v);
            } else {
                int rem = q - 768;
                int arr = rem >> 6;
                int r2  = rem & 63;
                int tq  = r2 >> 2;
                int v   = (r2 & 3) * 4;
                int t   = tbase + t0 + tq;
                if (arr == 0) cp_async16p(&s_B[buf][tq][v], g_proj + (size_t)t * NPROJ + DI + v);
                else          cp_async16p(&s_C[buf][tq][v], g_proj + (size_t)t * NPROJ + DI + NST + v);
            }
        }
        cp_commit();
    };

    issue(0, 0);
    int buf = 0;
    const int NT = CH / TT;
    for (int it = 0; it < NT; it++) {
        if (it + 1 < NT) { issue((it + 1) * TT, buf ^ 1); cp_wait<1>(); }
        else             { cp_wait<0>(); }
        __syncthreads();

        int t0 = tbase + it * TT;
#pragma unroll
        for (int tt = 0; tt < TT; tt++) {
            float del = s_delta[buf][tt][dl];
            float xv  = s_xi[buf][tt][dl];
            float4 bv = *(const float4*)&s_B[buf][tt][nq * 4];
            float4 cv = *(const float4*)&s_C[buf][tt][nq * 4];
            float dx = del * xv;
            float e0 = __expf(del * A0), e1 = __expf(del * A1);
            float e2 = __expf(del * A2), e3 = __expf(del * A3);
            h0 = fmaf(e0, h0, dx * bv.x);
            h1 = fmaf(e1, h1, dx * bv.y);
            h2 = fmaf(e2, h2, dx * bv.z);
            h3 = fmaf(e3, h3, dx * bv.w);
            float yv = h0 * cv.x;
            yv = fmaf(h1, cv.y, yv);
            yv = fmaf(h2, cv.z, yv);
            yv = fmaf(h3, cv.w, yv);
            yv += __shfl_xor_sync(0xffffffffu, yv, 1);
            yv += __shfl_xor_sync(0xffffffffu, yv, 2);
            if (nq == 0) {
                float r  = s_res[buf][tt][dl];
                float y  = fmaf(xv, Dd, yv);
                float zv = y * (r / (1.f + __expf(-r)));
                size_t o = (size_t)(t0 + tt) * DI + d;
                __half zh = __float2half_rn(zv);
                g_ahi[o] = zh;
                g_alo[o] = __float2half_rn(zv - __half2float(zh));
            }
        }
        __syncthreads();
        buf ^= 1;
    }
}

// ============================================================================
// launch
// ============================================================================
extern "C" void kernel_launch(void* const* d_in, const int* in_sizes, int n_in,
                              void* d_out, int out_size)
{
    const float* x      = (const float*)d_in[0];
    const float* W_in   = (const float*)d_in[1];
    const float* b_in   = (const float*)d_in[2];
    const float* W_conv = (const float*)d_in[3];
    const float* b_conv = (const float*)d_in[4];
    const float* W_x    = (const float*)d_in[5];
    const float* b_x    = (const float*)d_in[6];
    const float* W_out  = (const float*)d_in[7];
    const float* b_out  = (const float*)d_in[8];
    const float* A_log  = (const float*)d_in[9];
    const float* Dv     = (const float*)d_in[10];
    float* out = (float*)d_out;

    float *xr, *proj;
    __half *ahi, *alo, *win_h, *wx_h, *wout_h;
    cudaGetSymbolAddress((void**)&xr,     g_xr);
    cudaGetSymbolAddress((void**)&proj,   g_proj);
    cudaGetSymbolAddress((void**)&ahi,    g_ahi);
    cudaGetSymbolAddress((void**)&alo,    g_alo);
    cudaGetSymbolAddress((void**)&win_h,  g_win_h);
    cudaGetSymbolAddress((void**)&wx_h,   g_wx_h);
    cudaGetSymbolAddress((void**)&wout_h, g_wout_h);

    static bool attr_done = false;
    if (!attr_done) {
        cudaFuncSetAttribute(gemm_mma<0>, cudaFuncAttributeMaxDynamicSharedMemorySize, GEMM_SMEM);
        cudaFuncSetAttribute(gemm_mma<1>, cudaFuncAttributeMaxDynamicSharedMemorySize, GEMM_SMEM);
        attr_done = true;
    }

    // ---- all converts in one launch ----
    cvt_all<<<(N4_TOT + 255) / 256, 256>>>(x, W_in, W_x, W_out);

    // ---- GEMM1: xr = x @ W_in.T + b_in ----
    {
        dim3 grid((2 * DI) / 128, L_SEQ / 128);
        gemm_mma<0><<<grid, 256, GEMM_SMEM>>>(ahi, alo, win_h, b_in, xr,
                                              2 * DI, DM, 2 * DI);
    }
    // ---- conv + silu (produces GEMM2's fp16 A) ----
    conv_silu_k<<<(L_SEQ * DI / 4) / 256, 256>>>(W_conv, b_conv);

    // ---- GEMM2: proj = xi @ W_x.T + b_x (softplus on delta) ----
    {
        dim3 grid((NPROJ + 127) / 128, L_SEQ / 128);
        gemm_mma<1><<<grid, 256, GEMM_SMEM>>>(ahi, alo, wx_h, b_x, proj,
                                              NPROJ, DI, NPROJ);
    }
    // ---- chunked scan (p3 produces GEMM3's fp16 A) ----
    {
        dim3 g1(DI / SD, NCH);
        scan_p1<<<g1, 256>>>(A_log);
        scan_comb<<<(DI * NST) / 256, 256>>>();
        scan_p3<<<g1, 256>>>(A_log, Dv);
    }
    // ---- GEMM3: out = z @ W_out.T + b_out ----
    {
        dim3 grid(DM / 128, L_SEQ / 128);
        gemm_mma<0><<<grid, 256, GEMM_SMEM>>>(ahi, alo, wout_h, b_out, out,
                                              DM, DI, DM);
    }
}

// round 7
// speedup vs baseline: 1.0280x; 1.0280x over previous
#include <cuda_runtime.h>
#include <cuda_fp16.h>
#include <math.h>
#include <stdint.h>

// ---------------- problem constants ----------------
#define L_SEQ 2048
#define DM    1024
#define DI    2048
#define NST   16
#define KC    4
#define NPROJ (DI + 2*NST)   // 2080

#define NCH   16
#define CH    128
#define TT    16
#define SD    64

// ---------------- scratch (device globals) ----------------
__device__ float g_xr  [L_SEQ * 2 * DI];
__device__ float g_xi  [L_SEQ * DI];
__device__ float g_proj[L_SEQ * NPROJ];

__device__ __half g_ahi[L_SEQ * DI];
__device__ __half g_alo[L_SEQ * DI];
__device__ __half g_win_h [2 * DI * DM];
__device__ __half g_wx_h  [NPROJ * DI];
__device__ __half g_wout_h[DM * DI];

__device__ float g_cA[NCH * DI * NST];
__device__ float g_cB[NCH * DI * NST];
__device__ float g_h0[NCH * DI * NST];

__device__ __forceinline__ float softplus_f(float x) {
    return fmaxf(x, 0.f) + log1pf(expf(-fabsf(x)));
}

// ---------------- PTX helpers ----------------
__device__ __forceinline__ uint32_t smem_u32(const void* p) {
    uint32_t a;
    asm("{ .reg .u64 t; cvta.to.shared.u64 t, %1; cvt.u32.u64 %0, t; }" : "=r"(a) : "l"(p));
    return a;
}
__device__ __forceinline__ void cp_async16(uint32_t sm, const void* gm) {
    asm volatile("cp.async.ca.shared.global [%0], [%1], 16;" :: "r"(sm), "l"(gm));
}
__device__ __forceinline__ void cp_async16p(void* sm, const void* gm) {
    cp_async16(smem_u32(sm), gm);
}
__device__ __forceinline__ void cp_commit() { asm volatile("cp.async.commit_group;"); }
template<int N> __device__ __forceinline__ void cp_wait() {
    asm volatile("cp.async.wait_group %0;" :: "n"(N));
}
__device__ __forceinline__ void ldm_x4(uint32_t* r, uint32_t addr) {
    asm volatile("ldmatrix.sync.aligned.m8n8.x4.shared.b16 {%0,%1,%2,%3}, [%4];"
        : "=r"(r[0]), "=r"(r[1]), "=r"(r[2]), "=r"(r[3]) : "r"(addr));
}
__device__ __forceinline__ void mma_f16(float* d, const uint32_t* a, const uint32_t* b) {
    asm volatile(
        "mma.sync.aligned.m16n8k16.row.col.f32.f16.f16.f32 "
        "{%0,%1,%2,%3}, {%4,%5,%6,%7}, {%8,%9}, {%0,%1,%2,%3};"
        : "+f"(d[0]), "+f"(d[1]), "+f"(d[2]), "+f"(d[3])
        : "r"(a[0]), "r"(a[1]), "r"(a[2]), "r"(a[3]), "r"(b[0]), "r"(b[1]));
}

// ============================================================================
// One fused convert kernel: all weights -> fp16, x -> fp16 hi/lo.
// ============================================================================
#define N4_X   (L_SEQ * DM / 4)
#define N4_WIN (2 * DI * DM / 4)
#define N4_WX  (NPROJ * DI / 4)
#define N4_WO  (DM * DI / 4)
#define N4_TOT (N4_X + N4_WIN + N4_WX + N4_WO)

__global__ __launch_bounds__(256)
void cvt_all(const float* __restrict__ x, const float* __restrict__ W_in,
             const float* __restrict__ W_x, const float* __restrict__ W_out)
{
    int i = blockIdx.x * blockDim.x + threadIdx.x;
    if (i >= N4_TOT) return;

    if (i < N4_X) {
        float4 v = ((const float4*)x)[i];
        __half hx = __float2half_rn(v.x), hy = __float2half_rn(v.y);
        __half hz = __float2half_rn(v.z), hw = __float2half_rn(v.w);
        ((__half2*)g_ahi)[i*2+0] = __half2(hx, hy);
        ((__half2*)g_ahi)[i*2+1] = __half2(hz, hw);
        ((__half2*)g_alo)[i*2+0] = __half2(__float2half_rn(v.x - __half2float(hx)),
                                           __float2half_rn(v.y - __half2float(hy)));
        ((__half2*)g_alo)[i*2+1] = __half2(__float2half_rn(v.z - __half2float(hz)),
                                           __float2half_rn(v.w - __half2float(hw)));
        return;
    }
    const float* src; __half* dst; int j;
    if (i < N4_X + N4_WIN)              { j = i - N4_X;                  src = W_in;  dst = g_win_h; }
    else if (i < N4_X + N4_WIN + N4_WX) { j = i - N4_X - N4_WIN;         src = W_x;   dst = g_wx_h; }
    else                                { j = i - N4_X - N4_WIN - N4_WX; src = W_out; dst = g_wout_h; }
    float4 v = ((const float4*)src)[j];
    ((__half2*)dst)[j*2+0] = __half2(__float2half_rn(v.x), __float2half_rn(v.y));
    ((__half2*)dst)[j*2+1] = __half2(__float2half_rn(v.z), __float2half_rn(v.w));
}

// ============================================================================
// fp16 2-term emulated-fp32 GEMM via mma.sync m16n8k16.
// Block 128x128, BK=64, 8 warps (4M x 2N). 2-stage ring, 1 barrier/stage.
// Per k16: all 8 LDSM issued up-front, then 32 HMMAs (dependency slack).
// ============================================================================
#define ROWB  144                    // 64 halves data + 8 pad, bytes
#define MATB  (128 * ROWB)           // 18432 bytes per matrix tile
#define BUFB  (3 * MATB)             // Ahi, Alo, Wh
#define GEMM_SMEM (2 * BUFB)         // 110592

__device__ __forceinline__ void gemm_load_stage(
    uint32_t sb, int buf, int k0,
    const __half* __restrict__ Ahi, const __half* __restrict__ Alo,
    const __half* __restrict__ Wh,
    int m0, int n0, int Nc, int Kd, int tid)
{
    uint32_t base = sb + buf * BUFB;
#pragma unroll
    for (int it = 0; it < 12; it++) {
        int q   = tid + it * 256;
        int mat = q >> 10;         // 0:Ahi 1:Alo 2:Wh
        int rem = q & 1023;
        int row = rem >> 3;        // 0..127
        int ch  = rem & 7;         // 8 chunks of 16B
        uint32_t dst = base + mat * MATB + row * ROWB + ch * 16;
        const __half* src;
        if (mat < 2) {
            const __half* bp = (mat == 0) ? Ahi : Alo;
            src = bp + (size_t)(m0 + row) * Kd + k0 + ch * 8;
        } else {
            int wr = n0 + row; if (wr >= Nc) wr = Nc - 1;
            src = Wh + (size_t)wr * Kd + k0 + ch * 8;
        }
        cp_async16(dst, src);
    }
    cp_commit();
}

template<int ACT>
__global__ __launch_bounds__(256, 2)
void gemm_mma(const __half* __restrict__ Ahi, const __half* __restrict__ Alo,
              const __half* __restrict__ Wh,
              const float* __restrict__ bias, float* __restrict__ C,
              int Nc, int Kd, int ldc)
{
    extern __shared__ char smraw[];
    uint32_t sb = smem_u32(smraw);

    int tid  = threadIdx.x;
    int wid  = tid >> 5;
    int lane = tid & 31;
    int wm   = wid & 3;
    int wn   = wid >> 2;
    int m0 = blockIdx.y * 128;
    int n0 = blockIdx.x * 128;

    float acc[2][8][4];
#pragma unroll
    for (int i = 0; i < 2; i++)
#pragma unroll
        for (int j = 0; j < 8; j++)
#pragma unroll
            for (int k = 0; k < 4; k++) acc[i][j][k] = 0.f;

    int aRow = wm * 32 + (lane & 15);
    int aColHalf = (lane >> 4) << 3;               // 0 or 8
    int bRow = wn * 64 + ((lane >> 4) & 1) * 8 + (lane & 7);
    int bColHalf = ((lane >> 3) & 1) << 3;         // 0 or 8

    const int NSTAGE = Kd / 64;
    gemm_load_stage(sb, 0, 0, Ahi, Alo, Wh, m0, n0, Nc, Kd, tid);

    int buf = 0;
    for (int s = 0; s < NSTAGE; s++) {
        cp_wait<0>();
        __syncthreads();
        // Buffer buf^1 was last read during compute of stage s-1, which all
        // warps finished before this barrier -> safe to refill now.
        if (s + 1 < NSTAGE)
            gemm_load_stage(sb, buf ^ 1, (s + 1) * 64, Ahi, Alo, Wh, m0, n0, Nc, Kd, tid);

        uint32_t bA = sb + buf * BUFB;
        uint32_t bW = bA + 2 * MATB;
#pragma unroll
        for (int kc = 0; kc < 4; kc++) {
            int acol2 = (kc * 16 + aColHalf) * 2;
            int bcol2 = (kc * 16 + bColHalf) * 2;
            uint32_t ah[2][4], al[2][4], bh[4][4];
            // all fragment loads for this k16 first (LDS latency overlap)
#pragma unroll
            for (int mt = 0; mt < 2; mt++) {
                uint32_t off = (uint32_t)((aRow + mt * 16) * ROWB + acol2);
                ldm_x4(ah[mt], bA + off);
                ldm_x4(al[mt], bA + MATB + off);
            }
#pragma unroll
            for (int ntp = 0; ntp < 4; ntp++) {
                uint32_t off = (uint32_t)((bRow + ntp * 16) * ROWB + bcol2);
                ldm_x4(bh[ntp], bW + off);
            }
            // then 32 back-to-back HMMAs
#pragma unroll
            for (int ntp = 0; ntp < 4; ntp++) {
#pragma unroll
                for (int mt = 0; mt < 2; mt++) {
                    mma_f16(acc[mt][2*ntp+0], ah[mt], bh[ntp] + 0);
                    mma_f16(acc[mt][2*ntp+1], ah[mt], bh[ntp] + 2);
                    mma_f16(acc[mt][2*ntp+0], al[mt], bh[ntp] + 0);
                    mma_f16(acc[mt][2*ntp+1], al[mt], bh[ntp] + 2);
                }
            }
        }
        buf ^= 1;
    }

#pragma unroll
    for (int mt = 0; mt < 2; mt++) {
        int r0 = m0 + wm * 32 + mt * 16 + (lane >> 2);
#pragma unroll
        for (int nt = 0; nt < 8; nt++) {
            int c = n0 + wn * 64 + nt * 8 + 2 * (lane & 3);
            if (c < Nc) {
                float b0 = bias[c], b1 = bias[c + 1];
                float v0 = acc[mt][nt][0] + b0;
                float v1 = acc[mt][nt][1] + b1;
                float v2 = acc[mt][nt][2] + b0;
                float v3 = acc[mt][nt][3] + b1;
                if (ACT == 1) {
                    if (c     < DI) { v0 = softplus_f(v0); v2 = softplus_f(v2); }
                    if (c + 1 < DI) { v1 = softplus_f(v1); v3 = softplus_f(v3); }
                }
                *(float2*)&C[(size_t)r0 * ldc + c]       = make_float2(v0, v1);
                *(float2*)&C[(size_t)(r0 + 8) * ldc + c] = make_float2(v2, v3);
            }
        }
    }
}

// ============================================================================
// Depthwise causal conv (K=4) + silu, 4 channels/thread.
// ============================================================================
__global__ __launch_bounds__(256)
void conv_silu_k(const float* __restrict__ Wc, const float* __restrict__ bc)
{
    int idx = blockIdx.x * blockDim.x + threadIdx.x;
    int t  = idx >> 9;
    int d4 = (idx & 511) << 2;

    float4 acc = *(const float4*)&bc[d4];
#pragma unroll
    for (int k = 0; k < KC; k++) {
        int tt = t - (KC - 1) + k;
        if (tt >= 0) {
            float4 v = *(const float4*)&g_xr[(size_t)tt * (2 * DI) + d4];
            acc.x = fmaf(Wc[(d4 + 0) * KC + k], v.x, acc.x);
            acc.y = fmaf(Wc[(d4 + 1) * KC + k], v.y, acc.y);
            acc.z = fmaf(Wc[(d4 + 2) * KC + k], v.z, acc.z);
            acc.w = fmaf(Wc[(d4 + 3) * KC + k], v.w, acc.w);
        }
    }
    float s0 = acc.x / (1.f + __expf(-acc.x));
    float s1 = acc.y / (1.f + __expf(-acc.y));
    float s2 = acc.z / (1.f + __expf(-acc.z));
    float s3 = acc.w / (1.f + __expf(-acc.w));
    size_t o = (size_t)t * DI + d4;
    *(float4*)&g_xi[o] = make_float4(s0, s1, s2, s3);
    __half h0 = __float2half_rn(s0), h1 = __float2half_rn(s1);
    __half h2 = __float2half_rn(s2), h3 = __float2half_rn(s3);
    *(__half2*)&g_ahi[o]     = __half2(h0, h1);
    *(__half2*)&g_ahi[o + 2] = __half2(h2, h3);
    *(__half2*)&g_alo[o]     = __half2(__float2half_rn(s0 - __half2float(h0)),
                                       __float2half_rn(s1 - __half2float(h1)));
    *(__half2*)&g_alo[o + 2] = __half2(__float2half_rn(s2 - __half2float(h2)),
                                       __float2half_rn(s3 - __half2float(h3)));
}

// ============================================================================
// Chunked selective scan (unchanged numerics).
// ============================================================================
__global__ __launch_bounds__(256, 1)
void scan_p1(const float* __restrict__ A_log)
{
    __shared__ float s_delta[2][TT][SD];
    __shared__ float s_xi   [2][TT][SD];
    __shared__ float s_B    [2][TT][NST];

    int tid = threadIdx.x;
    int nq = tid & 3;
    int dl = tid >> 2;
    int dbase = blockIdx.x * SD;
    int d = dbase + dl;
    int chunk = blockIdx.y;
    int tbase = chunk * CH;

    float4 alv = *(const float4*)&A_log[d * NST + nq * 4];
    float A0 = -__expf(alv.x), A1 = -__expf(alv.y);
    float A2 = -__expf(alv.z), A3 = -__expf(alv.w);

    float ap0 = 1.f, ap1 = 1.f, ap2 = 1.f, ap3 = 1.f;
    float h0 = 0.f, h1 = 0.f, h2 = 0.f, h3 = 0.f;

    auto issue = [&](int t0, int buf) {
        for (int q = tid; q < 576; q += 256) {
            if (q < 512) {
                int arr = q >> 8;
                int rem = q & 255;
                int tq  = rem >> 4;
                int v   = (rem & 15) * 4;
                int t   = tbase + t0 + tq;
                if (arr == 0)
                    cp_async16p(&s_delta[buf][tq][v], g_proj + (size_t)t * NPROJ + dbase + v);
                else
                    cp_async16p(&s_xi[buf][tq][v], g_xi + (size_t)t * DI + dbase + v);
            } else {
                int rem = q - 512;
                int tq  = rem >> 2;
                int v   = (rem & 3) * 4;
                int t   = tbase + t0 + tq;
                cp_async16p(&s_B[buf][tq][v], g_proj + (size_t)t * NPROJ + DI + v);
            }
        }
        cp_commit();
    };

    issue(0, 0);
    int buf = 0;
    const int NT = CH / TT;
    for (int it = 0; it < NT; it++) {
        if (it + 1 < NT) { issue((it + 1) * TT, buf ^ 1); cp_wait<1>(); }
        else             { cp_wait<0>(); }
        __syncthreads();
#pragma unroll
        for (int tt = 0; tt < TT; tt++) {
            float del = s_delta[buf][tt][dl];
            float xv  = s_xi[buf][tt][dl];
            float4 bv = *(const float4*)&s_B[buf][tt][nq * 4];
            float dx = del * xv;
            float e0 = __expf(del * A0), e1 = __expf(del * A1);
            float e2 = __expf(del * A2), e3 = __expf(del * A3);
            ap0 *= e0; ap1 *= e1; ap2 *= e2; ap3 *= e3;
            h0 = fmaf(e0, h0, dx * bv.x);
            h1 = fmaf(e1, h1, dx * bv.y);
            h2 = fmaf(e2, h2, dx * bv.z);
            h3 = fmaf(e3, h3, dx * bv.w);
        }
        __syncthreads();
        buf ^= 1;
    }
    int idx = (chunk * DI + d) * NST + nq * 4;
    *(float4*)&g_cA[idx] = make_float4(ap0, ap1, ap2, ap3);
    *(float4*)&g_cB[idx] = make_float4(h0, h1, h2, h3);
}

__global__ __launch_bounds__(256)
void scan_comb()
{
    int dn = blockIdx.x * blockDim.x + threadIdx.x;
    float h = 0.f;
#pragma unroll
    for (int c = 0; c < NCH; c++) {
        int idx = c * (DI * NST) + dn;
        g_h0[idx] = h;
        h = fmaf(g_cA[idx], h, g_cB[idx]);
    }
}

__global__ __launch_bounds__(256, 1)
void scan_p3(const float* __restrict__ A_log, const float* __restrict__ Dv)
{
    __shared__ float s_delta[2][TT][SD];
    __shared__ float s_xi   [2][TT][SD];
    __shared__ float s_res  [2][TT][SD];
    __shared__ float s_B    [2][TT][NST];
    __shared__ float s_C    [2][TT][NST];

    int tid = threadIdx.x;
    int nq = tid & 3;
    int dl = tid >> 2;
    int dbase = blockIdx.x * SD;
    int d = dbase + dl;
    int chunk = blockIdx.y;
    int tbase = chunk * CH;

    float4 alv = *(const float4*)&A_log[d * NST + nq * 4];
    float A0 = -__expf(alv.x), A1 = -__expf(alv.y);
    float A2 = -__expf(alv.z), A3 = -__expf(alv.w);
    float Dd = Dv[d];

    float4 hv = *(const float4*)&g_h0[(chunk * DI + d) * NST + nq * 4];
    float h0 = hv.x, h1 = hv.y, h2 = hv.z, h3 = hv.w;

    auto issue = [&](int t0, int buf) {
        for (int q = tid; q < 896; q += 256) {
            if (q < 768) {
                int arr = q >> 8;
                int rem = q & 255;
                int tq  = rem >> 4;
                int v   = (rem & 15) * 4;
                int t   = tbase + t0 + tq;
                if      (arr == 0) cp_async16p(&s_delta[buf][tq][v], g_proj + (size_t)t * NPROJ + dbase + v);
                else if (arr == 1) cp_async16p(&s_xi[buf][tq][v],    g_xi   + (size_t)t * DI + dbase + v);
                else               cp_async16p(&s_res[buf][tq][v],   g_xr   + (size_t)t * (2*DI) + DI + dbase + v);
            } else {
                int rem = q - 768;
                int arr = rem >> 6;
                int r2  = rem & 63;
                int tq  = r2 >> 2;
                int v   = (r2 & 3) * 4;
                int t   = tbase + t0 + tq;
                if (arr == 0) cp_async16p(&s_B[buf][tq][v], g_proj + (size_t)t * NPROJ + DI + v);
                else          cp_async16p(&s_C[buf][tq][v], g_proj + (size_t)t * NPROJ + DI + NST + v);
            }
        }
        cp_commit();
    };

    issue(0, 0);
    int buf = 0;
    const int NT = CH / TT;
    for (int it = 0; it < NT; it++) {
        if (it + 1 < NT) { issue((it + 1) * TT, buf ^ 1); cp_wait<1>(); }
        else             { cp_wait<0>(); }
        __syncthreads();

        int t0 = tbase + it * TT;
#pragma unroll
        for (int tt = 0; tt < TT; tt++) {
            float del = s_delta[buf][tt][dl];
            float xv  = s_xi[buf][tt][dl];
            float4 bv = *(const float4*)&s_B[buf][tt][nq * 4];
            float4 cv = *(const float4*)&s_C[buf][tt][nq * 4];
            float dx = del * xv;
            float e0 = __expf(del * A0), e1 = __expf(del * A1);
            float e2 = __expf(del * A2), e3 = __expf(del * A3);
            h0 = fmaf(e0, h0, dx * bv.x);
            h1 = fmaf(e1, h1, dx * bv.y);
            h2 = fmaf(e2, h2, dx * bv.z);
            h3 = fmaf(e3, h3, dx * bv.w);
            float yv = h0 * cv.x;
            yv = fmaf(h1, cv.y, yv);
            yv = fmaf(h2, cv.z, yv);
            yv = fmaf(h3, cv.w, yv);
            yv += __shfl_xor_sync(0xffffffffu, yv, 1);
            yv += __shfl_xor_sync(0xffffffffu, yv, 2);
            if (nq == 0) {
                float r  = s_res[buf][tt][dl];
                float y  = fmaf(xv, Dd, yv);
                float zv = y * (r / (1.f + __expf(-r)));
                size_t o = (size_t)(t0 + tt) * DI + d;
                __half zh = __float2half_rn(zv);
                g_ahi[o] = zh;
                g_alo[o] = __float2half_rn(zv - __half2float(zh));
            }
        }
        __syncthreads();
        buf ^= 1;
    }
}

// ============================================================================
// launch
// ============================================================================
extern "C" void kernel_launch(void* const* d_in, const int* in_sizes, int n_in,
                              void* d_out, int out_size)
{
    const float* x      = (const float*)d_in[0];
    const float* W_in   = (const float*)d_in[1];
    const float* b_in   = (const float*)d_in[2];
    const float* W_conv = (const float*)d_in[3];
    const float* b_conv = (const float*)d_in[4];
    const float* W_x    = (const float*)d_in[5];
    const float* b_x    = (const float*)d_in[6];
    const float* W_out  = (const float*)d_in[7];
    const float* b_out  = (const float*)d_in[8];
    const float* A_log  = (const float*)d_in[9];
    const float* Dv     = (const float*)d_in[10];
    float* out = (float*)d_out;

    float *xr, *proj;
    __half *ahi, *alo, *win_h, *wx_h, *wout_h;
    cudaGetSymbolAddress((void**)&xr,     g_xr);
    cudaGetSymbolAddress((void**)&proj,   g_proj);
    cudaGetSymbolAddress((void**)&ahi,    g_ahi);
    cudaGetSymbolAddress((void**)&alo,    g_alo);
    cudaGetSymbolAddress((void**)&win_h,  g_win_h);
    cudaGetSymbolAddress((void**)&wx_h,   g_wx_h);
    cudaGetSymbolAddress((void**)&wout_h, g_wout_h);

    static bool attr_done = false;
    if (!attr_done) {
        cudaFuncSetAttribute(gemm_mma<0>, cudaFuncAttributeMaxDynamicSharedMemorySize, GEMM_SMEM);
        cudaFuncSetAttribute(gemm_mma<1>, cudaFuncAttributeMaxDynamicSharedMemorySize, GEMM_SMEM);
        attr_done = true;
    }

    cvt_all<<<(N4_TOT + 255) / 256, 256>>>(x, W_in, W_x, W_out);

    {   // GEMM1: xr = x @ W_in.T + b_in
        dim3 grid((2 * DI) / 128, L_SEQ / 128);
        gemm_mma<0><<<grid, 256, GEMM_SMEM>>>(ahi, alo, win_h, b_in, xr,
                                              2 * DI, DM, 2 * DI);
    }
    conv_silu_k<<<(L_SEQ * DI / 4) / 256, 256>>>(W_conv, b_conv);

    {   // GEMM2: proj = xi @ W_x.T + b_x (softplus on delta)
        dim3 grid((NPROJ + 127) / 128, L_SEQ / 128);
        gemm_mma<1><<<grid, 256, GEMM_SMEM>>>(ahi, alo, wx_h, b_x, proj,
                                              NPROJ, DI, NPROJ);
    }
    {   // chunked scan
        dim3 g1(DI / SD, NCH);
        scan_p1<<<g1, 256>>>(A_log);
        scan_comb<<<(DI * NST) / 256, 256>>>();
        scan_p3<<<g1, 256>>>(A_log, Dv);
    }
    {   // GEMM3: out = z @ W_out.T + b_out
        dim3 grid(DM / 128, L_SEQ / 128);
        gemm_mma<0><<<grid, 256, GEMM_SMEM>>>(ahi, alo, wout_h, b_out, out,
                                              DM, DI, DM);
    }
}